// round 10
// baseline (speedup 1.0000x reference)
#include <cuda_runtime.h>
#include <cuda_bf16.h>
#include <cstdint>

#define BB 128
#define SS 128
#define NN 784
#define DD 512
#define NT 112
#define N_ITERS 10
#define EPS_F 2.2204460492503131e-16f
#define QF (1.0f / 784.0f)
#define PF (1.0f / 128.0f)

// ---------------- device scratch ----------------
__device__ float g_K[(size_t)BB * SS * NN];          // 51.4 MB
__device__ __nv_bfloat16 g_thi[SS * DD];             // normalized target, bf16 hi
__device__ __nv_bfloat16 g_tlo[SS * DD];             // residual lo

// ---------------- helpers ----------------
__device__ __forceinline__ uint32_t smem_u32(const void* p) {
    uint32_t a;
    asm("{ .reg .u64 t; cvta.to.shared.u64 t, %1; cvt.u32.u64 %0, t; }" : "=r"(a) : "l"(p));
    return a;
}
__device__ __forceinline__ unsigned short bf_bits(__nv_bfloat16 h) {
    return *reinterpret_cast<unsigned short*>(&h);
}
__device__ __forceinline__ void ldm_x4(uint32_t* r, uint32_t addr) {
    asm volatile("ldmatrix.sync.aligned.m8n8.x4.shared.b16 {%0,%1,%2,%3}, [%4];"
                 : "=r"(r[0]), "=r"(r[1]), "=r"(r[2]), "=r"(r[3]) : "r"(addr));
}
__device__ __forceinline__ void ldm_x2(uint32_t* r, uint32_t addr) {
    asm volatile("ldmatrix.sync.aligned.m8n8.x2.shared.b16 {%0,%1}, [%2];"
                 : "=r"(r[0]), "=r"(r[1]) : "r"(addr));
}
__device__ __forceinline__ void mma16816(float* c, const uint32_t* a, const uint32_t* b) {
    asm volatile("mma.sync.aligned.m16n8k16.row.col.f32.bf16.bf16.f32 "
                 "{%0,%1,%2,%3}, {%4,%5,%6,%7}, {%8,%9}, {%0,%1,%2,%3};"
                 : "+f"(c[0]), "+f"(c[1]), "+f"(c[2]), "+f"(c[3])
                 : "r"(a[0]), "r"(a[1]), "r"(a[2]), "r"(a[3]), "r"(b[0]), "r"(b[1]));
}
#define CP16(dst, src) \
    asm volatile("cp.async.cg.shared.global [%0], [%1], 16;" :: "r"(dst), "l"(src))
#define CP_COMMIT() asm volatile("cp.async.commit_group;")
#define CP_WAIT0()  asm volatile("cp.async.wait_group 0;")
#define CP_WAIT1()  asm volatile("cp.async.wait_group 1;")

// ---------------- kernel 1: normalize target + split hi/lo bf16 ----------------
__global__ void norm_target_kernel(const float* __restrict__ t) {
    int s = blockIdx.x;
    int tid = threadIdx.x;  // 128 threads, 4 cols each
    __shared__ float red[4];
    const float4* tr = (const float4*)(t + (size_t)s * DD);
    float4 v = tr[tid];
    float ss = v.x * v.x + v.y * v.y + v.z * v.z + v.w * v.w;
    #pragma unroll
    for (int o = 16; o; o >>= 1) ss += __shfl_xor_sync(0xffffffffu, ss, o);
    if ((tid & 31) == 0) red[tid >> 5] = ss;
    __syncthreads();
    float inv = rsqrtf(red[0] + red[1] + red[2] + red[3]);

    float x[4] = {v.x * inv, v.y * inv, v.z * inv, v.w * inv};
    unsigned short h[4], l[4];
    #pragma unroll
    for (int i = 0; i < 4; i++) {
        __nv_bfloat16 hb = __float2bfloat16(x[i]);
        h[i] = bf_bits(hb);
        l[i] = bf_bits(__float2bfloat16(x[i] - __bfloat162float(hb)));
    }
    *(ushort4*)&g_thi[s * DD + tid * 4] = make_ushort4(h[0], h[1], h[2], h[3]);
    *(ushort4*)&g_tlo[s * DD + tid * 4] = make_ushort4(l[0], l[1], l[2], l[3]);
}

// ---------------- kernel 2: split-bf16 mma.sync GEMM + exp epilogue ----------------
// D[s,n] = sum_k tn[s,k]*fn[n,k] via hh + lh + hl, then K = exp(20*D - 20)
#define KC   64
#define LDA  72            // bf16 elements per smem row (64 + 8 pad)
#define OF_RN 0            // 448 B
#define OF_AH 512
#define OF_AL (OF_AH + 128 * LDA * 2)   // +18432
#define OF_BH (OF_AL + 128 * LDA * 2)
#define OF_BL (OF_BH + NT * LDA * 2)    // +16128
#define GEMM_SMEM (OF_BL + NT * LDA * 2)

__global__ __launch_bounds__(256, 2) void gemm_mma_kernel(const float* __restrict__ f) {
    extern __shared__ unsigned char smem[];
    const int b   = blockIdx.y;
    const int n0  = blockIdx.x * NT;
    const int tid = threadIdx.x;
    const int wid  = tid >> 5;
    const int lane = tid & 31;
    const int sgrp = wid & 3;          // S block of 32
    const int ngrp = wid >> 2;         // N block of 56
    uint32_t sb = smem_u32(smem);
    float* rn_s = (float*)(smem + OF_RN);

    const float* fb = f + (size_t)b * NN * DD;

    // prologue: inverse norms of this CTA's 112 feature rows (one warp per row)
    for (int r = wid; r < NT; r += 8) {
        const float4* fr = (const float4*)(fb + (size_t)(n0 + r) * DD);
        float ssum = 0.f;
        #pragma unroll
        for (int i = lane; i < DD / 4; i += 32) {
            float4 v = fr[i];
            ssum += v.x * v.x + v.y * v.y + v.z * v.z + v.w * v.w;
        }
        #pragma unroll
        for (int o = 16; o; o >>= 1) ssum += __shfl_xor_sync(0xffffffffu, ssum, o);
        if (lane == 0) rn_s[r] = rsqrtf(ssum);
    }
    __syncthreads();

    float acc[2][7][4];
    #pragma unroll
    for (int mt = 0; mt < 2; mt++)
        #pragma unroll
        for (int nt = 0; nt < 7; nt++)
            #pragma unroll
            for (int i = 0; i < 4; i++) acc[mt][nt][i] = 0.f;

    for (int c = 0; c < 8; ++c) {
        if (c) __syncthreads();     // previous chunk fully consumed

        // A tiles: cp.async pre-split bf16 hi/lo (L2-resident, 128 x 64)
        #pragma unroll
        for (int i = tid; i < 1024; i += 256) {
            int s = i >> 3, seg = i & 7;
            int go = s * DD + c * KC + seg * 8;
            uint32_t so = (s * LDA + seg * 8) * 2;
            CP16(sb + OF_AH + so, g_thi + go);
            CP16(sb + OF_AL + so, g_tlo + go);
        }
        CP_COMMIT();

        // B tiles: load f32 features, fold rn, split, STS
        for (int u = tid; u < NT * 8; u += 256) {
            int r = u >> 3, seg = u & 7;
            const float4* src = (const float4*)(fb + (size_t)(n0 + r) * DD + c * KC + seg * 8);
            float4 v0 = src[0], v1 = src[1];
            float rr = rn_s[r];
            float x[8] = {v0.x * rr, v0.y * rr, v0.z * rr, v0.w * rr,
                          v1.x * rr, v1.y * rr, v1.z * rr, v1.w * rr};
            uint32_t H[4], L[4];
            #pragma unroll
            for (int i = 0; i < 4; i++) {
                __nv_bfloat16 h0 = __float2bfloat16(x[2 * i]);
                __nv_bfloat16 h1 = __float2bfloat16(x[2 * i + 1]);
                __nv_bfloat16 l0 = __float2bfloat16(x[2 * i] - __bfloat162float(h0));
                __nv_bfloat16 l1 = __float2bfloat16(x[2 * i + 1] - __bfloat162float(h1));
                H[i] = (uint32_t)bf_bits(h0) | ((uint32_t)bf_bits(h1) << 16);
                L[i] = (uint32_t)bf_bits(l0) | ((uint32_t)bf_bits(l1) << 16);
            }
            uint32_t so = (r * LDA + seg * 8) * 2;
            *(uint4*)(smem + OF_BH + so) = make_uint4(H[0], H[1], H[2], H[3]);
            *(uint4*)(smem + OF_BL + so) = make_uint4(L[0], L[1], L[2], L[3]);
        }
        CP_WAIT0();
        __syncthreads();

        // compute: 4 k-steps of 16
        const int arow = sgrp * 32 + (lane & 15);
        const int acol = (lane >> 4) * 8;
        const int l2 = lane & 15;
        const int bcol = (lane >> 4) * 8;   // threads 16-31 fetch the k+8 half
        #pragma unroll
        for (int ks = 0; ks < 4; ks++) {
            const int kk = ks * 16;
            uint32_t ah[2][4], al[2][4], bf[7][2];
            #pragma unroll
            for (int mt = 0; mt < 2; mt++) {
                uint32_t ao = ((arow + mt * 16) * LDA + kk + acol) * 2;
                ldm_x4(ah[mt], sb + OF_AH + ao);
                ldm_x4(al[mt], sb + OF_AL + ao);
            }
            // B hi fragments: 3 pairs via x4 + 1 via x2
            #pragma unroll
            for (int p = 0; p < 3; p++) {
                uint32_t r4[4];
                ldm_x4(r4, sb + OF_BH + ((ngrp * 56 + p * 16 + l2) * LDA + kk + bcol) * 2);
                bf[2 * p][0] = r4[0]; bf[2 * p][1] = r4[2];
                bf[2 * p + 1][0] = r4[1]; bf[2 * p + 1][1] = r4[3];
            }
            ldm_x2(bf[6], sb + OF_BH + ((ngrp * 56 + 48 + (l2 & 7)) * LDA + kk + (l2 >> 3) * 8) * 2);
            #pragma unroll
            for (int mt = 0; mt < 2; mt++)
                #pragma unroll
                for (int nt = 0; nt < 7; nt++) {
                    mma16816(acc[mt][nt], ah[mt], bf[nt]);   // hi*hi
                    mma16816(acc[mt][nt], al[mt], bf[nt]);   // lo*hi
                }
            // B lo fragments (reuse regs)
            #pragma unroll
            for (int p = 0; p < 3; p++) {
                uint32_t r4[4];
                ldm_x4(r4, sb + OF_BL + ((ngrp * 56 + p * 16 + l2) * LDA + kk + bcol) * 2);
                bf[2 * p][0] = r4[0]; bf[2 * p][1] = r4[2];
                bf[2 * p + 1][0] = r4[1]; bf[2 * p + 1][1] = r4[3];
            }
            ldm_x2(bf[6], sb + OF_BL + ((ngrp * 56 + 48 + (l2 & 7)) * LDA + kk + (l2 >> 3) * 8) * 2);
            #pragma unroll
            for (int mt = 0; mt < 2; mt++)
                #pragma unroll
                for (int nt = 0; nt < 7; nt++)
                    mma16816(acc[mt][nt], ah[mt], bf[nt]);   // hi*lo
        }
    }

    // epilogue: K = exp(20*acc - 20), direct store (rows contiguous in n)
    const int g = lane >> 2;
    const int t2 = (lane & 3) * 2;
    #pragma unroll
    for (int mt = 0; mt < 2; mt++) {
        int srow0 = sgrp * 32 + mt * 16 + g;
        float* kr0 = g_K + ((size_t)b * SS + srow0) * NN + n0 + ngrp * 56;
        float* kr1 = kr0 + 8 * NN;
        #pragma unroll
        for (int nt = 0; nt < 7; nt++) {
            int cc = nt * 8 + t2;
            kr0[cc]     = __expf(fmaf(acc[mt][nt][0], 20.f, -20.f));
            kr0[cc + 1] = __expf(fmaf(acc[mt][nt][1], 20.f, -20.f));
            kr1[cc]     = __expf(fmaf(acc[mt][nt][2], 20.f, -20.f));
            kr1[cc + 1] = __expf(fmaf(acc[mt][nt][3], 20.f, -20.f));
        }
    }
}

// ---------------- kernel 3: fused Sinkhorn, ONE pass over K per iteration ----------------
// Per tile (128 s x 112 n, smem, double-buffered cp.async):
//   phase 1: col sums A[n] = sum_s su[s]*K[s,n]  -> sv[n] = q/(A+eps)
//   phase 2: accumulate accu[s] += sum_{n in tile} sv[n]*K[s,n]  (registers, warp-distributed)
// End of iteration: su[s] = p/(accu[s]+eps).  Final pass: phase2 writes Pi instead.
#define TNS 112
#define NTILES 7
#define TILE_FLOATS (SS * TNS)          // 14336
#define TILE_BYTES  (TILE_FLOATS * 4)   // 57344
#define SOF_AP (2 * TILE_BYTES)         // Apart[8][112]
#define SOF_SV (SOF_AP + 8 * TNS * 4)
#define SOF_SU (SOF_SV + TNS * 4)
#define SINK_SMEM (SOF_SU + SS * 4)     // 119232

__global__ __launch_bounds__(1024, 1) void sinkhorn_kernel(float* __restrict__ Pi) {
    extern __shared__ unsigned char dsm[];
    float* Kt    = (float*)dsm;
    float* Apart = (float*)(dsm + SOF_AP);
    float* sv_s  = (float*)(dsm + SOF_SV);
    float* su    = (float*)(dsm + SOF_SU);

    const int b = blockIdx.x;
    const int tid = threadIdx.x;
    const int warp = tid >> 5;
    const int lane = tid & 31;
    const float* __restrict__ Kb = g_K + (size_t)b * SS * NN;
    const uint32_t sb = smem_u32(dsm);

    if (tid < SS) su[tid] = 1.0f;

    // tile loader: 3584 float4 per tile, contiguous 28 float4 per K row
    auto load_tile = [&](int t, int buf) {
        const float* src = Kb + t * TNS;
        const uint32_t dst = sb + buf * TILE_BYTES;
        #pragma unroll
        for (int i = tid; i < 3584; i += 1024) {
            int s = i / 28, j = i % 28;
            CP16(dst + (uint32_t)(s * TNS + j * 4) * 4, src + (size_t)s * NN + j * 4);
        }
        CP_COMMIT();
    };

    load_tile(0, 0);

    const int pg = tid / TNS;            // phase-1 group 0..7 (tid<896)
    const int pc = tid - pg * TNS;       // phase-1 column
    float accu[4] = {0.f, 0.f, 0.f, 0.f};
    const int TOTAL = (N_ITERS + 1) * NTILES;
    int gt = 0;

    for (int it = 0; it <= N_ITERS; it++) {
        for (int t = 0; t < NTILES; t++, gt++) {
            const int buf = gt & 1;
            __syncthreads();                         // prev phase2 done; su update visible
            if (gt + 1 < TOTAL) {
                load_tile((t + 1) % NTILES, buf ^ 1);
                CP_WAIT1();
            } else {
                CP_WAIT0();
            }
            __syncthreads();                         // current tile resident

            const float* kt = Kt + buf * TILE_FLOATS;

            // phase 1: partial column sums (896 threads: 8 groups x 112 cols)
            if (tid < 896) {
                const float* kc = kt + pc;
                const int s0 = pg * 16;
                float a0 = 0.f, a1 = 0.f;
                #pragma unroll
                for (int s = 0; s < 16; s += 2) {
                    a0 = fmaf(su[s0 + s],     kc[(s0 + s) * TNS],     a0);
                    a1 = fmaf(su[s0 + s + 1], kc[(s0 + s + 1) * TNS], a1);
                }
                Apart[pg * TNS + pc] = a0 + a1;
            }
            __syncthreads();
            if (tid < TNS) {
                float a = 0.f;
                #pragma unroll
                for (int g = 0; g < 8; g++) a += Apart[g * TNS + tid];
                sv_s[tid] = QF / (a + EPS_F);
            }
            __syncthreads();

            // phase 2: warp w owns rows 4w..4w+3; lane covers cols lane,+32,+64,+96
            const float v0 = sv_s[lane];
            const float v1 = sv_s[lane + 32];
            const float v2 = sv_s[lane + 64];
            const float v3 = (lane < 16) ? sv_s[lane + 96] : 0.f;
            if (it < N_ITERS) {
                #pragma unroll
                for (int j = 0; j < 4; j++) {
                    const float* kr = kt + (warp * 4 + j) * TNS;
                    float a = fmaf(v0, kr[lane], 0.f);
                    a = fmaf(v1, kr[lane + 32], a);
                    a = fmaf(v2, kr[lane + 64], a);
                    if (lane < 16) a = fmaf(v3, kr[lane + 96], a);
                    accu[j] += a;
                }
            } else {
                float* Pb = Pi + (size_t)b * SS * NN + t * TNS;
                #pragma unroll
                for (int j = 0; j < 4; j++) {
                    const int s = warp * 4 + j;
                    const float* kr = kt + s * TNS;
                    float* pr = Pb + (size_t)s * NN;
                    const float us = su[s];
                    pr[lane]      = us * kr[lane]      * v0;
                    pr[lane + 32] = us * kr[lane + 32] * v1;
                    pr[lane + 64] = us * kr[lane + 64] * v2;
                    if (lane < 16) pr[lane + 96] = us * kr[lane + 96] * v3;
                }
            }
        }
        if (it < N_ITERS) {
            #pragma unroll
            for (int j = 0; j < 4; j++) {
                float a = accu[j];
                #pragma unroll
                for (int o = 16; o; o >>= 1) a += __shfl_xor_sync(0xffffffffu, a, o);
                if (lane == 0) su[warp * 4 + j] = PF / (a + EPS_F);
                accu[j] = 0.f;
            }
            // next tile's leading __syncthreads orders su before phase 1
        }
    }
}

// ---------------- launcher ----------------
extern "C" void kernel_launch(void* const* d_in, const int* in_sizes, int n_in,
                              void* d_out, int out_size) {
    const float* features = (const float*)d_in[0];
    const float* target   = (const float*)d_in[1];
    if (n_in >= 2 && in_sizes[0] == SS * DD) {
        const float* tmp = features; features = target; target = tmp;
    }
    float* Pi = (float*)d_out;

    cudaFuncSetAttribute(gemm_mma_kernel,
                         cudaFuncAttributeMaxDynamicSharedMemorySize, GEMM_SMEM);
    cudaFuncSetAttribute(sinkhorn_kernel,
                         cudaFuncAttributeMaxDynamicSharedMemorySize, SINK_SMEM);

    norm_target_kernel<<<SS, 128>>>(target);
    gemm_mma_kernel<<<dim3(7, BB), 256, GEMM_SMEM>>>(features);
    sinkhorn_kernel<<<BB, 1024, SINK_SMEM>>>(Pi);
}